// round 9
// baseline (speedup 1.0000x reference)
#include <cuda_runtime.h>
#include <cuda_bf16.h>
#include <cstdint>
#include <math.h>

#define Bb 2
#define Nn 512
#define Cc 256
#define Hh 256
#define Ww 256
#define POOLP 7
#define SRR 2
#define OUTD 1024
#define DIN (Cc*POOLP*POOLP)   // 12544
#define RR (Bb*Nn)             // 1024
#define NCLS 11
#define PI_F 3.14159265358979323846f

// GEMM tiling (mma.sync path)
#define BM 128
#define BN 128
#define BK 32
#define KSP 40                       // padded smem K-stride (halves) -> 80B rows
#define TB (128*KSP*2)               // 10240 bytes per operand tile
#define STAGE (4*TB)                 // Ahi,Alo,Bhi,Blo = 40960
#define NSTAGE 3
#define SMEM_GEMM (NSTAGE*STAGE)     // 122880 B

// ------------------------- device scratch (no cudaMalloc) -------------------
__device__ float g_feat_hwc[(size_t)Bb*Hh*Ww*Cc];            // 134 MB NHWC
__device__ __nv_bfloat16 g_Xhi[(size_t)RR*DIN];
__device__ __nv_bfloat16 g_Xlo[(size_t)RR*DIN];
__device__ __nv_bfloat16 g_W1hi[(size_t)OUTD*DIN];           // [N,K] K-major
__device__ __nv_bfloat16 g_W1lo[(size_t)OUTD*DIN];
__device__ __nv_bfloat16 g_W2hi[(size_t)OUTD*OUTD];
__device__ __nv_bfloat16 g_W2lo[(size_t)OUTD*OUTD];
__device__ float g_P[(size_t)2*RR*OUTD];                     // split-K partials
__device__ __nv_bfloat16 g_H1hi[RR*OUTD];
__device__ __nv_bfloat16 g_H1lo[RR*OUTD];
__device__ float g_H2[RR*OUTD];

// ------------------------- helpers ------------------------------------------
__device__ __forceinline__ void cp16(uint32_t s, const void* g) {
    asm volatile("cp.async.cg.shared.global [%0], [%1], 16;" :: "r"(s), "l"(g));
}
__device__ __forceinline__ void ldsm4(uint32_t* r, uint32_t addr) {
    asm volatile("ldmatrix.sync.aligned.m8n8.x4.shared.b16 {%0,%1,%2,%3}, [%4];"
                 : "=r"(r[0]), "=r"(r[1]), "=r"(r[2]), "=r"(r[3]) : "r"(addr));
}
#define MMA_BF16(D, A, B0, B1)                                                  \
    asm volatile("mma.sync.aligned.m16n8k16.row.col.f32.bf16.bf16.f32 "         \
                 "{%0,%1,%2,%3}, {%4,%5,%6,%7}, {%8,%9}, {%0,%1,%2,%3};"        \
                 : "+f"((D)[0]), "+f"((D)[1]), "+f"((D)[2]), "+f"((D)[3])       \
                 : "r"((A)[0]), "r"((A)[1]), "r"((A)[2]), "r"((A)[3]),          \
                   "r"(B0), "r"(B1))

// ---------------------------------------------------------------------------
// 1) NCHW -> NHWC transpose
// ---------------------------------------------------------------------------
__global__ void transpose_kernel(const float* __restrict__ in) {
    __shared__ float tile[32][33];
    int b = blockIdx.z;
    const float* A = in + (size_t)b * Cc * Hh * Ww;
    float* O = g_feat_hwc + (size_t)b * Cc * Hh * Ww;
    int p0 = blockIdx.x * 32;
    int c0 = blockIdx.y * 32;
    #pragma unroll
    for (int i = threadIdx.y; i < 32; i += 8)
        tile[i][threadIdx.x] = A[(size_t)(c0 + i) * (Hh * Ww) + p0 + threadIdx.x];
    __syncthreads();
    #pragma unroll
    for (int i = threadIdx.y; i < 32; i += 8)
        O[(size_t)(p0 + i) * Cc + c0 + threadIdx.x] = tile[threadIdx.x][i];
}

// ---------------------------------------------------------------------------
// 1b) Weight transpose + bf16 hi/lo split: W[K,N] -> T{hi,lo}[N,K]
// ---------------------------------------------------------------------------
__global__ void wsplit_kernel(const float* __restrict__ W, __nv_bfloat16* __restrict__ Thi,
                              __nv_bfloat16* __restrict__ Tlo, int K, int N) {
    __shared__ float tile[32][33];
    int k0 = blockIdx.x * 32, n0 = blockIdx.y * 32;
    int tx = threadIdx.x, ty = threadIdx.y;
    #pragma unroll
    for (int i = ty; i < 32; i += 8)
        tile[i][tx] = W[(size_t)(k0 + i) * N + n0 + tx];
    __syncthreads();
    #pragma unroll
    for (int i = ty; i < 32; i += 8) {
        float v = tile[tx][i];
        __nv_bfloat16 h = __float2bfloat16(v);
        size_t o = (size_t)(n0 + i) * K + k0 + tx;
        Thi[o] = h;
        Tlo[o] = __float2bfloat16(v - __bfloat162float(h));
    }
}

// ---------------------------------------------------------------------------
// 2) Rotated ROI align -> X (bf16 hi/lo)  [R5 configuration]
// ---------------------------------------------------------------------------
__global__ void roi_align_kernel(const float* __restrict__ proposals) {
    __shared__ float4 s_w[POOLP*POOLP*SRR*SRR];
    __shared__ int4   s_o[POOLP*POOLP*SRR*SRR];
    __shared__ float  s_out[128*49];

    int r = blockIdx.x;
    int chunk = blockIdx.y;
    int b = r / Nn;
    int tid = threadIdx.x;

    const float* pr = proposals + r * 5;
    float cx = pr[0], cy = pr[1], w = pr[2], h = pr[3], th = pr[4];
    float ct = cosf(th), st = sinf(th);

    for (int s = tid; s < POOLP*POOLP*SRR*SRR; s += 128) {
        int bin = s >> 2;
        int by = bin / POOLP, bx = bin % POOLP;
        int sub = s & 3;
        int sy = sub >> 1, sx = sub & 1;
        float yy = -h * 0.5f + (h / (float)POOLP) * ((float)by + ((float)sy + 0.5f) / (float)SRR);
        float xx = -w * 0.5f + (w / (float)POOLP) * ((float)bx + ((float)sx + 0.5f) / (float)SRR);
        float gx = cx + xx * ct - yy * st;
        float gy = cy + xx * st + yy * ct;
        float valid = (gy > -1.f && gy < (float)Hh && gx > -1.f && gx < (float)Ww) ? 1.f : 0.f;
        gy = fminf(fmaxf(gy, 0.f), (float)(Hh - 1));
        gx = fminf(fmaxf(gx, 0.f), (float)(Ww - 1));
        float y0 = floorf(gy), x0 = floorf(gx);
        int y0i = (int)y0, x0i = (int)x0;
        int y1i = min(y0i + 1, Hh - 1), x1i = min(x0i + 1, Ww - 1);
        float ly = gy - y0, lx = gx - x0;
        float hy = 1.f - ly, hx = 1.f - lx;
        float sc = valid * 0.25f;
        s_w[s] = make_float4(hy*hx*sc, hy*lx*sc, ly*hx*sc, ly*lx*sc);
        s_o[s] = make_int4(y0i*Ww + x0i, y0i*Ww + x1i, y1i*Ww + x0i, y1i*Ww + x1i);
    }
    __syncthreads();

    const float* F = g_feat_hwc + (size_t)b * Hh * Ww * Cc;
    int c = chunk * 128 + tid;

    for (int bin = 0; bin < POOLP*POOLP; bin++) {
        float acc = 0.f;
        #pragma unroll
        for (int s = 0; s < 4; s++) {
            int si = bin * 4 + s;
            float4 wv = s_w[si];
            int4   ov = s_o[si];
            acc += wv.x * F[(size_t)ov.x * Cc + c];
            acc += wv.y * F[(size_t)ov.y * Cc + c];
            acc += wv.z * F[(size_t)ov.z * Cc + c];
            acc += wv.w * F[(size_t)ov.w * Cc + c];
        }
        s_out[tid * 49 + bin] = acc;
    }
    __syncthreads();

    size_t base = (size_t)r * DIN + (size_t)chunk * 128 * 49;
    for (int d = tid; d < 128 * 49; d += 128) {
        float v = s_out[d];
        __nv_bfloat16 hv = __float2bfloat16(v);
        g_Xhi[base + d] = hv;
        g_Xlo[base + d] = __float2bfloat16(v - __bfloat162float(hv));
    }
}

// ---------------------------------------------------------------------------
// 3) mma.sync bf16x3 GEMM. 256 threads, 8 warps (64x32 warp tiles),
//    3-stage cp.async pipeline. C = A*B^T, K-major hi/lo operands.
// ---------------------------------------------------------------------------
template<bool BIAS_RELU>
__global__ void __launch_bounds__(256, 1)
mma_gemm(const __nv_bfloat16* __restrict__ Ahi, const __nv_bfloat16* __restrict__ Alo,
         const __nv_bfloat16* __restrict__ Bhi, const __nv_bfloat16* __restrict__ Blo,
         const float* __restrict__ bias, float* __restrict__ Cout,
         int Ksplit, size_t ldk, int Ntot) {
    extern __shared__ char smem[];
    uint32_t sb = (uint32_t)__cvta_generic_to_shared(smem);
    int tid = threadIdx.x;
    int lane = tid & 31, wid = tid >> 5;
    int wm = wid & 1, wn = wid >> 1;              // warps: 2 along M, 4 along N
    int n0 = blockIdx.x * BN, m0 = blockIdx.y * BM, z = blockIdx.z;
    int kbase = z * Ksplit;
    int S = Ksplit / BK;

    // stage loader: 4 tiles of 128x32 bf16 into padded smem
    auto stage_load = [&](int s, int bufi) {
        uint32_t buf = sb + bufi * STAGE;
        int kc = kbase + s * BK;
        #pragma unroll
        for (int i = 0; i < 2; i++) {
            int idx = tid + i * 256;
            int row = idx >> 2, kq = idx & 3;
            uint32_t so = (uint32_t)(row * (KSP * 2) + kq * 16);
            size_t ga = (size_t)(m0 + row) * ldk + kc + kq * 8;
            size_t gb = (size_t)(n0 + row) * ldk + kc + kq * 8;
            cp16(buf + 0 * TB + so, Ahi + ga);
            cp16(buf + 1 * TB + so, Alo + ga);
            cp16(buf + 2 * TB + so, Bhi + gb);
            cp16(buf + 3 * TB + so, Blo + gb);
        }
        asm volatile("cp.async.commit_group;");
    };

    float acc[4][4][4] = {};

    // ldmatrix lane->address offsets
    int aRow = lane & 15;
    int aK   = (lane >> 4) * 8;
    int bRow = (lane & 7) + ((lane >> 4) << 3);
    int bK   = ((lane >> 3) & 1) * 8;

    stage_load(0, 0);
    if (S > 1) stage_load(1, 1);
    int bufi = 0;
    for (int s = 0; s < S; s++) {
        if (s > 0) __syncthreads();            // readers of recycled buffer done
        if (s + 2 < S) {
            int nb = bufi + 2; if (nb >= NSTAGE) nb -= NSTAGE;
            stage_load(s + 2, nb);
            asm volatile("cp.async.wait_group 2;");
        } else if (s + 1 < S) {
            asm volatile("cp.async.wait_group 1;");
        } else {
            asm volatile("cp.async.wait_group 0;");
        }
        __syncthreads();

        uint32_t buf = sb + bufi * STAGE;
        #pragma unroll
        for (int kk = 0; kk < 2; kk++) {
            int kb = kk * 16;
            uint32_t ah[4][4], al[4][4], bh[8], bl[8];
            #pragma unroll
            for (int mt = 0; mt < 4; mt++) {
                uint32_t ro = (uint32_t)((wm * 64 + mt * 16 + aRow) * (KSP * 2) + (kb + aK) * 2);
                ldsm4(ah[mt], buf + 0 * TB + ro);
                ldsm4(al[mt], buf + 1 * TB + ro);
            }
            #pragma unroll
            for (int nh = 0; nh < 2; nh++) {
                uint32_t ro = (uint32_t)((wn * 32 + nh * 16 + bRow) * (KSP * 2) + (kb + bK) * 2);
                ldsm4(&bh[nh * 4], buf + 2 * TB + ro);
                ldsm4(&bl[nh * 4], buf + 3 * TB + ro);
            }
            #pragma unroll
            for (int mt = 0; mt < 4; mt++)
                #pragma unroll
                for (int nt = 0; nt < 4; nt++) {
                    MMA_BF16(acc[mt][nt], ah[mt], bh[nt * 2], bh[nt * 2 + 1]);
                    MMA_BF16(acc[mt][nt], al[mt], bh[nt * 2], bh[nt * 2 + 1]);
                    MMA_BF16(acc[mt][nt], ah[mt], bl[nt * 2], bl[nt * 2 + 1]);
                }
        }
        bufi = (bufi + 1 == NSTAGE) ? 0 : bufi + 1;
    }

    // epilogue
    int drow = lane >> 2, dcol = (lane & 3) * 2;
    float* Cz = Cout + (size_t)z * RR * OUTD;
    #pragma unroll
    for (int mt = 0; mt < 4; mt++) {
        int m = m0 + wm * 64 + mt * 16 + drow;
        #pragma unroll
        for (int nt = 0; nt < 4; nt++) {
            int n = n0 + wn * 32 + nt * 8 + dcol;
            float v0 = acc[mt][nt][0], v1 = acc[mt][nt][1];
            float v2 = acc[mt][nt][2], v3 = acc[mt][nt][3];
            if (BIAS_RELU) {
                v0 = fmaxf(v0 + bias[n], 0.f);     v1 = fmaxf(v1 + bias[n + 1], 0.f);
                v2 = fmaxf(v2 + bias[n], 0.f);     v3 = fmaxf(v3 + bias[n + 1], 0.f);
            }
            *reinterpret_cast<float2*>(Cz + (size_t)m * Ntot + n) = make_float2(v0, v1);
            *reinterpret_cast<float2*>(Cz + (size_t)(m + 8) * Ntot + n) = make_float2(v2, v3);
        }
    }
}

// ---------------------------------------------------------------------------
// 3b) split-K combine + bias + relu -> H1 bf16 hi/lo
// ---------------------------------------------------------------------------
__global__ void combine_kernel(const float* __restrict__ b1) {
    int i = blockIdx.x * 256 + threadIdx.x;
    float v = g_P[i] + g_P[(size_t)RR*OUTD + i] + b1[i & (OUTD - 1)];
    v = fmaxf(v, 0.f);
    __nv_bfloat16 h = __float2bfloat16(v);
    g_H1hi[i] = h;
    g_H1lo[i] = __float2bfloat16(v - __bfloat162float(h));
}

// ---------------------------------------------------------------------------
// 4) Head: cls/reg dots + box decode
// ---------------------------------------------------------------------------
__global__ void head_kernel(const float* __restrict__ X,
                            const float* __restrict__ Wcls, const float* __restrict__ bcls,
                            const float* __restrict__ Wreg, const float* __restrict__ breg,
                            const float* __restrict__ proposals, float* __restrict__ out) {
    __shared__ float xs[OUTD];
    __shared__ float red[16][8];
    __shared__ float regv[5];
    int r = blockIdx.x, t = threadIdx.x;
    const float* xr = X + (size_t)r * OUTD;
    for (int i = t; i < OUTD / 4; i += 128)
        ((float4*)xs)[i] = ((const float4*)xr)[i];
    __syncthreads();

    int j = t & 15, part = t >> 4;
    float acc = 0.f;
    if (j < NCLS) {
        for (int k = part * 128; k < part * 128 + 128; k++)
            acc += xs[k] * Wcls[k * NCLS + j];
    } else {
        int jr = j - NCLS;
        for (int k = part * 128; k < part * 128 + 128; k++)
            acc += xs[k] * Wreg[k * 5 + jr];
    }
    red[j][part] = acc;
    __syncthreads();

    if (t < 16) {
        float s = 0.f;
        #pragma unroll
        for (int p = 0; p < 8; p++) s += red[t][p];
        if (t < NCLS) {
            out[RR * 5 + r * NCLS + t] = s + bcls[t];
        } else {
            regv[t - NCLS] = s + breg[t - NCLS];
        }
    }
    __syncthreads();

    if (t == 0) {
        const float* pr = proposals + r * 5;
        float px = pr[0] * 4.f, py = pr[1] * 4.f;
        float pw = pr[2] * 4.f, ph = pr[3] * 4.f, pa = pr[4];
        const float clampv = 4.135166556742356f;
        float bx = pw * regv[0] + px;
        float by = ph * regv[1] + py;
        float bw = pw * expf(fminf(fmaxf(regv[2], -clampv), clampv));
        float bh = ph * expf(fminf(fmaxf(regv[3], -clampv), clampv));
        float a = pa + regv[4] + PI_F * 0.5f;
        float m = fmodf(a, PI_F);
        if (m < 0.f) m += PI_F;
        out[r * 5 + 0] = bx;
        out[r * 5 + 1] = by;
        out[r * 5 + 2] = bw;
        out[r * 5 + 3] = bh;
        out[r * 5 + 4] = m - PI_F * 0.5f;
    }
}

// ---------------------------------------------------------------------------
extern "C" void kernel_launch(void* const* d_in, const int* in_sizes, int n_in,
                              void* d_out, int out_size) {
    const float* feat      = (const float*)d_in[0];
    const float* proposals = (const float*)d_in[1];
    const float* W1   = (const float*)d_in[2];
    const float* b1   = (const float*)d_in[3];
    const float* W2   = (const float*)d_in[4];
    const float* b2   = (const float*)d_in[5];
    const float* Wcls = (const float*)d_in[6];
    const float* bcls = (const float*)d_in[7];
    const float* Wreg = (const float*)d_in[8];
    const float* breg = (const float*)d_in[9];
    float* out = (float*)d_out;

    __nv_bfloat16 *pXhi, *pXlo, *pW1hi, *pW1lo, *pW2hi, *pW2lo, *pH1hi, *pH1lo;
    float *pP, *pH2;
    cudaGetSymbolAddress((void**)&pXhi,  g_Xhi);
    cudaGetSymbolAddress((void**)&pXlo,  g_Xlo);
    cudaGetSymbolAddress((void**)&pW1hi, g_W1hi);
    cudaGetSymbolAddress((void**)&pW1lo, g_W1lo);
    cudaGetSymbolAddress((void**)&pW2hi, g_W2hi);
    cudaGetSymbolAddress((void**)&pW2lo, g_W2lo);
    cudaGetSymbolAddress((void**)&pH1hi, g_H1hi);
    cudaGetSymbolAddress((void**)&pH1lo, g_H1lo);
    cudaGetSymbolAddress((void**)&pP,    g_P);
    cudaGetSymbolAddress((void**)&pH2,   g_H2);

    cudaFuncSetAttribute(mma_gemm<false>, cudaFuncAttributeMaxDynamicSharedMemorySize, SMEM_GEMM);
    cudaFuncSetAttribute(mma_gemm<true>,  cudaFuncAttributeMaxDynamicSharedMemorySize, SMEM_GEMM);

    // weight transpose + split (independent of feat path)
    wsplit_kernel<<<dim3(DIN/32, OUTD/32), dim3(32, 8)>>>(W1, pW1hi, pW1lo, DIN, OUTD);
    wsplit_kernel<<<dim3(OUTD/32, OUTD/32), dim3(32, 8)>>>(W2, pW2hi, pW2lo, OUTD, OUTD);

    transpose_kernel<<<dim3(Hh*Ww/32, Cc/32, Bb), dim3(32, 8)>>>(feat);
    roi_align_kernel<<<dim3(RR, 2), 128>>>(proposals);

    // GEMM1: X(1024x12544) * W1^T -> split-K=2 partials
    mma_gemm<false><<<dim3(OUTD/BN, RR/BM, 2), 256, SMEM_GEMM>>>(
        pXhi, pXlo, pW1hi, pW1lo, nullptr, pP, DIN/2, (size_t)DIN, OUTD);
    combine_kernel<<<RR*OUTD/256, 256>>>(b1);

    // GEMM2: H1(1024x1024) * W2^T -> H2 (bias+relu fused)
    mma_gemm<true><<<dim3(OUTD/BN, RR/BM, 1), 256, SMEM_GEMM>>>(
        pH1hi, pH1lo, pW2hi, pW2lo, b2, pH2, OUTD, (size_t)OUTD, OUTD);

    head_kernel<<<RR, 128>>>(pH2, Wcls, bcls, Wreg, breg, proposals, out);
}

// round 12
// speedup vs baseline: 1.3407x; 1.3407x over previous
#include <cuda_runtime.h>
#include <cuda_fp16.h>
#include <cstdint>
#include <math.h>

#define Bb 2
#define Nn 512
#define Cc 256
#define Hh 256
#define Ww 256
#define POOLP 7
#define SRR 2
#define OUTD 1024
#define DIN (Cc*POOLP*POOLP)   // 12544
#define RR (Bb*Nn)             // 1024
#define NCLS 11
#define PI_F 3.14159265358979323846f

// GEMM tiling (mma.sync path, fp16 2-term: Ahi*B + Alo*B)
#define BM 128
#define BN 128
#define BK 32
#define KSP 40                       // padded smem K-stride (halves) -> 80B rows
#define TB (128*KSP*2)               // 10240 bytes per operand tile
#define STAGE (3*TB)                 // Ahi, Alo, B = 30720
#define SMEM_GEMM (2*STAGE)          // 61440 B double buffered -> 2 CTAs/SM

// ------------------------- device scratch (no cudaMalloc) -------------------
__device__ float g_feat_hwc[(size_t)Bb*Hh*Ww*Cc];            // 134 MB NHWC
__device__ __half g_Xhi[(size_t)RR*DIN];
__device__ __half g_Xlo[(size_t)RR*DIN];
__device__ __half g_W1[(size_t)OUTD*DIN];                    // [N,K] K-major fp16
__device__ __half g_W2[(size_t)OUTD*OUTD];
__device__ float g_P[(size_t)4*RR*OUTD];                     // split-K partials
__device__ __half g_H1hi[RR*OUTD];
__device__ __half g_H1lo[RR*OUTD];
__device__ float g_H2[RR*OUTD];

// ------------------------- helpers ------------------------------------------
__device__ __forceinline__ void cp16(uint32_t s, const void* g) {
    asm volatile("cp.async.cg.shared.global [%0], [%1], 16;" :: "r"(s), "l"(g));
}
__device__ __forceinline__ void ldsm4(uint32_t* r, uint32_t addr) {
    asm volatile("ldmatrix.sync.aligned.m8n8.x4.shared.b16 {%0,%1,%2,%3}, [%4];"
                 : "=r"(r[0]), "=r"(r[1]), "=r"(r[2]), "=r"(r[3]) : "r"(addr));
}
#define MMA_F16(D, A, B0, B1)                                                   \
    asm volatile("mma.sync.aligned.m16n8k16.row.col.f32.f16.f16.f32 "           \
                 "{%0,%1,%2,%3}, {%4,%5,%6,%7}, {%8,%9}, {%0,%1,%2,%3};"        \
                 : "+f"((D)[0]), "+f"((D)[1]), "+f"((D)[2]), "+f"((D)[3])       \
                 : "r"((A)[0]), "r"((A)[1]), "r"((A)[2]), "r"((A)[3]),          \
                   "r"(B0), "r"(B1))

// ---------------------------------------------------------------------------
// 1) NCHW -> NHWC transpose
// ---------------------------------------------------------------------------
__global__ void transpose_kernel(const float* __restrict__ in) {
    __shared__ float tile[32][33];
    int b = blockIdx.z;
    const float* A = in + (size_t)b * Cc * Hh * Ww;
    float* O = g_feat_hwc + (size_t)b * Cc * Hh * Ww;
    int p0 = blockIdx.x * 32;
    int c0 = blockIdx.y * 32;
    #pragma unroll
    for (int i = threadIdx.y; i < 32; i += 8)
        tile[i][threadIdx.x] = A[(size_t)(c0 + i) * (Hh * Ww) + p0 + threadIdx.x];
    __syncthreads();
    #pragma unroll
    for (int i = threadIdx.y; i < 32; i += 8)
        O[(size_t)(p0 + i) * Cc + c0 + threadIdx.x] = tile[threadIdx.x][i];
}

// ---------------------------------------------------------------------------
// 1b) Weight transpose + fp16 convert: W[K,N] -> T[N,K]
// ---------------------------------------------------------------------------
__global__ void wconv_kernel(const float* __restrict__ W, __half* __restrict__ T,
                             int K, int N) {
    __shared__ float tile[32][33];
    int k0 = blockIdx.x * 32, n0 = blockIdx.y * 32;
    int tx = threadIdx.x, ty = threadIdx.y;
    #pragma unroll
    for (int i = ty; i < 32; i += 8)
        tile[i][tx] = W[(size_t)(k0 + i) * N + n0 + tx];
    __syncthreads();
    #pragma unroll
    for (int i = ty; i < 32; i += 8)
        T[(size_t)(n0 + i) * K + k0 + tx] = __float2half(tile[tx][i]);
}

// ---------------------------------------------------------------------------
// 2) Rotated ROI align -> X (fp16 hi/lo)  [R5 structure]
// ---------------------------------------------------------------------------
__global__ void roi_align_kernel(const float* __restrict__ proposals) {
    __shared__ float4 s_w[POOLP*POOLP*SRR*SRR];
    __shared__ int4   s_o[POOLP*POOLP*SRR*SRR];
    __shared__ float  s_out[128*49];

    int r = blockIdx.x;
    int chunk = blockIdx.y;
    int b = r / Nn;
    int tid = threadIdx.x;

    const float* pr = proposals + r * 5;
    float cx = pr[0], cy = pr[1], w = pr[2], h = pr[3], th = pr[4];
    float ct = cosf(th), st = sinf(th);

    for (int s = tid; s < POOLP*POOLP*SRR*SRR; s += 128) {
        int bin = s >> 2;
        int by = bin / POOLP, bx = bin % POOLP;
        int sub = s & 3;
        int sy = sub >> 1, sx = sub & 1;
        float yy = -h * 0.5f + (h / (float)POOLP) * ((float)by + ((float)sy + 0.5f) / (float)SRR);
        float xx = -w * 0.5f + (w / (float)POOLP) * ((float)bx + ((float)sx + 0.5f) / (float)SRR);
        float gx = cx + xx * ct - yy * st;
        float gy = cy + xx * st + yy * ct;
        float valid = (gy > -1.f && gy < (float)Hh && gx > -1.f && gx < (float)Ww) ? 1.f : 0.f;
        gy = fminf(fmaxf(gy, 0.f), (float)(Hh - 1));
        gx = fminf(fmaxf(gx, 0.f), (float)(Ww - 1));
        float y0 = floorf(gy), x0 = floorf(gx);
        int y0i = (int)y0, x0i = (int)x0;
        int y1i = min(y0i + 1, Hh - 1), x1i = min(x0i + 1, Ww - 1);
        float ly = gy - y0, lx = gx - x0;
        float hy = 1.f - ly, hx = 1.f - lx;
        float sc = valid * 0.25f;
        s_w[s] = make_float4(hy*hx*sc, hy*lx*sc, ly*hx*sc, ly*lx*sc);
        s_o[s] = make_int4(y0i*Ww + x0i, y0i*Ww + x1i, y1i*Ww + x0i, y1i*Ww + x1i);
    }
    __syncthreads();

    const float* F = g_feat_hwc + (size_t)b * Hh * Ww * Cc;
    int c = chunk * 128 + tid;

    for (int bin = 0; bin < POOLP*POOLP; bin++) {
        float acc = 0.f;
        #pragma unroll
        for (int s = 0; s < 4; s++) {
            int si = bin * 4 + s;
            float4 wv = s_w[si];
            int4   ov = s_o[si];
            acc += wv.x * F[(size_t)ov.x * Cc + c];
            acc += wv.y * F[(size_t)ov.y * Cc + c];
            acc += wv.z * F[(size_t)ov.z * Cc + c];
            acc += wv.w * F[(size_t)ov.w * Cc + c];
        }
        s_out[tid * 49 + bin] = acc;
    }
    __syncthreads();

    size_t base = (size_t)r * DIN + (size_t)chunk * 128 * 49;
    for (int d = tid; d < 128 * 49; d += 128) {
        float v = s_out[d];
        __half hv = __float2half(v);
        g_Xhi[base + d] = hv;
        g_Xlo[base + d] = __float2half(v - __half2float(hv));
    }
}

// ---------------------------------------------------------------------------
// 3) mma.sync fp16 2-term GEMM. 8 warps (64x32 warp tiles), 2-stage pipeline
//    [exact R5 loop structure]. P[z] = (Ahi + Alo) * B^T, K-major operands.
// ---------------------------------------------------------------------------
__global__ void __launch_bounds__(256, 2)
mma_gemm(const __half* __restrict__ Ahi, const __half* __restrict__ Alo,
         const __half* __restrict__ Bw, float* __restrict__ Pout,
         int Ksplit, size_t ldk) {
    extern __shared__ char smem[];
    uint32_t sb = (uint32_t)__cvta_generic_to_shared(smem);
    int tid = threadIdx.x;
    int lane = tid & 31, wid = tid >> 5;
    int wm = wid & 1, wn = wid >> 1;              // warps: 2 along M, 4 along N
    int n0 = blockIdx.x * BN, m0 = blockIdx.y * BM, z = blockIdx.z;
    int kbase = z * Ksplit;
    int S = Ksplit / BK;

    // stage loader: 3 tiles of 128x32 fp16 into padded smem
    auto stage_load = [&](int s) {
        uint32_t buf = sb + (s & 1) * STAGE;
        int kc = kbase + s * BK;
        #pragma unroll
        for (int i = 0; i < 2; i++) {
            int idx = tid + i * 256;
            int row = idx >> 2, kq = idx & 3;
            uint32_t so = (uint32_t)(row * (KSP * 2) + kq * 16);
            size_t ga = (size_t)(m0 + row) * ldk + kc + kq * 8;
            size_t gb = (size_t)(n0 + row) * ldk + kc + kq * 8;
            cp16(buf + 0 * TB + so, Ahi + ga);
            cp16(buf + 1 * TB + so, Alo + ga);
            cp16(buf + 2 * TB + so, Bw + gb);
        }
        asm volatile("cp.async.commit_group;");
    };

    float acc[4][4][4] = {};

    // ldmatrix lane->address offsets
    int aRow = lane & 15;
    int aK   = (lane >> 4) * 8;
    int bRow = (lane & 7) + ((lane >> 4) << 3);
    int bK   = ((lane >> 3) & 1) * 8;

    stage_load(0);
    for (int s = 0; s < S; s++) {
        if (s + 1 < S) {
            stage_load(s + 1);
            asm volatile("cp.async.wait_group 1;");
        } else {
            asm volatile("cp.async.wait_group 0;");
        }
        __syncthreads();

        uint32_t buf = sb + (s & 1) * STAGE;
        #pragma unroll
        for (int kk = 0; kk < 2; kk++) {
            int kb = kk * 16;
            uint32_t ah[4][4], al[4][4], bw[8];
            #pragma unroll
            for (int mt = 0; mt < 4; mt++) {
                uint32_t ro = (uint32_t)((wm * 64 + mt * 16 + aRow) * (KSP * 2) + (kb + aK) * 2);
                ldsm4(ah[mt], buf + 0 * TB + ro);
                ldsm4(al[mt], buf + 1 * TB + ro);
            }
            #pragma unroll
            for (int nh = 0; nh < 2; nh++) {
                uint32_t ro = (uint32_t)((wn * 32 + nh * 16 + bRow) * (KSP * 2) + (kb + bK) * 2);
                ldsm4(&bw[nh * 4], buf + 2 * TB + ro);
            }
            #pragma unroll
            for (int mt = 0; mt < 4; mt++)
                #pragma unroll
                for (int nt = 0; nt < 4; nt++) {
                    MMA_F16(acc[mt][nt], ah[mt], bw[nt * 2], bw[nt * 2 + 1]);
                    MMA_F16(acc[mt][nt], al[mt], bw[nt * 2], bw[nt * 2 + 1]);
                }
        }
        __syncthreads();
    }

    // epilogue: raw partials (bias applied in combine)
    int drow = lane >> 2, dcol = (lane & 3) * 2;
    float* Cz = Pout + (size_t)z * RR * OUTD;
    #pragma unroll
    for (int mt = 0; mt < 4; mt++) {
        int m = m0 + wm * 64 + mt * 16 + drow;
        #pragma unroll
        for (int nt = 0; nt < 4; nt++) {
            int n = n0 + wn * 32 + nt * 8 + dcol;
            *reinterpret_cast<float2*>(Cz + (size_t)m * OUTD + n) =
                make_float2(acc[mt][nt][0], acc[mt][nt][1]);
            *reinterpret_cast<float2*>(Cz + (size_t)(m + 8) * OUTD + n) =
                make_float2(acc[mt][nt][2], acc[mt][nt][3]);
        }
    }
}

// ---------------------------------------------------------------------------
// 3b) combine1: sum 4 split-K partials + bias + relu -> H1 fp16 hi/lo
// ---------------------------------------------------------------------------
__global__ void combine1_kernel(const float* __restrict__ b1) {
    int i = blockIdx.x * 256 + threadIdx.x;
    const size_t st = (size_t)RR * OUTD;
    float v = g_P[i] + g_P[st + i] + g_P[2*st + i] + g_P[3*st + i] + b1[i & (OUTD - 1)];
    v = fmaxf(v, 0.f);
    __half h = __float2half(v);
    g_H1hi[i] = h;
    g_H1lo[i] = __float2half(v - __half2float(h));
}

// 3c) combine2: sum 2 split-K partials + bias + relu -> H2 fp32
__global__ void combine2_kernel(const float* __restrict__ b2) {
    int i = blockIdx.x * 256 + threadIdx.x;
    const size_t st = (size_t)RR * OUTD;
    float v = g_P[i] + g_P[st + i] + b2[i & (OUTD - 1)];
    g_H2[i] = fmaxf(v, 0.f);
}

// ---------------------------------------------------------------------------
// 4) Head: cls/reg dots + box decode
// ---------------------------------------------------------------------------
__global__ void head_kernel(const float* __restrict__ X,
                            const float* __restrict__ Wcls, const float* __restrict__ bcls,
                            const float* __restrict__ Wreg, const float* __restrict__ breg,
                            const float* __restrict__ proposals, float* __restrict__ out) {
    __shared__ float xs[OUTD];
    __shared__ float red[16][8];
    __shared__ float regv[5];
    int r = blockIdx.x, t = threadIdx.x;
    const float* xr = X + (size_t)r * OUTD;
    for (int i = t; i < OUTD / 4; i += 128)
        ((float4*)xs)[i] = ((const float4*)xr)[i];
    __syncthreads();

    int j = t & 15, part = t >> 4;
    float acc = 0.f;
    if (j < NCLS) {
        for (int k = part * 128; k < part * 128 + 128; k++)
            acc += xs[k] * Wcls[k * NCLS + j];
    } else {
        int jr = j - NCLS;
        for (int k = part * 128; k < part * 128 + 128; k++)
            acc += xs[k] * Wreg[k * 5 + jr];
    }
    red[j][part] = acc;
    __syncthreads();

    if (t < 16) {
        float s = 0.f;
        #pragma unroll
        for (int p = 0; p < 8; p++) s += red[t][p];
        if (t < NCLS) {
            out[RR * 5 + r * NCLS + t] = s + bcls[t];
        } else {
            regv[t - NCLS] = s + breg[t - NCLS];
        }
    }
    __syncthreads();

    if (t == 0) {
        const float* pr = proposals + r * 5;
        float px = pr[0] * 4.f, py = pr[1] * 4.f;
        float pw = pr[2] * 4.f, ph = pr[3] * 4.f, pa = pr[4];
        const float clampv = 4.135166556742356f;
        float bx = pw * regv[0] + px;
        float by = ph * regv[1] + py;
        float bw = pw * expf(fminf(fmaxf(regv[2], -clampv), clampv));
        float bh = ph * expf(fminf(fmaxf(regv[3], -clampv), clampv));
        float a = pa + regv[4] + PI_F * 0.5f;
        float m = fmodf(a, PI_F);
        if (m < 0.f) m += PI_F;
        out[r * 5 + 0] = bx;
        out[r * 5 + 1] = by;
        out[r * 5 + 2] = bw;
        out[r * 5 + 3] = bh;
        out[r * 5 + 4] = m - PI_F * 0.5f;
    }
}

// ---------------------------------------------------------------------------
extern "C" void kernel_launch(void* const* d_in, const int* in_sizes, int n_in,
                              void* d_out, int out_size) {
    const float* feat      = (const float*)d_in[0];
    const float* proposals = (const float*)d_in[1];
    const float* W1   = (const float*)d_in[2];
    const float* b1   = (const float*)d_in[3];
    const float* W2   = (const float*)d_in[4];
    const float* b2   = (const float*)d_in[5];
    const float* Wcls = (const float*)d_in[6];
    const float* bcls = (const float*)d_in[7];
    const float* Wreg = (const float*)d_in[8];
    const float* breg = (const float*)d_in[9];
    float* out = (float*)d_out;

    __half *pXhi, *pXlo, *pW1, *pW2, *pH1hi, *pH1lo;
    float *pP, *pH2;
    cudaGetSymbolAddress((void**)&pXhi,  g_Xhi);
    cudaGetSymbolAddress((void**)&pXlo,  g_Xlo);
    cudaGetSymbolAddress((void**)&pW1,   g_W1);
    cudaGetSymbolAddress((void**)&pW2,   g_W2);
    cudaGetSymbolAddress((void**)&pH1hi, g_H1hi);
    cudaGetSymbolAddress((void**)&pH1lo, g_H1lo);
    cudaGetSymbolAddress((void**)&pP,    g_P);
    cudaGetSymbolAddress((void**)&pH2,   g_H2);

    cudaFuncSetAttribute(mma_gemm, cudaFuncAttributeMaxDynamicSharedMemorySize, SMEM_GEMM);

    // weight transpose + fp16 convert (independent of feat path)
    wconv_kernel<<<dim3(DIN/32, OUTD/32), dim3(32, 8)>>>(W1, pW1, DIN, OUTD);
    wconv_kernel<<<dim3(OUTD/32, OUTD/32), dim3(32, 8)>>>(W2, pW2, OUTD, OUTD);

    transpose_kernel<<<dim3(Hh*Ww/32, Cc/32, Bb), dim3(32, 8)>>>(feat);
    roi_align_kernel<<<dim3(RR, 2), 128>>>(proposals);

    // GEMM1: X(1024x12544) * W1^T -> split-K=4 partials (256 CTAs, occ 2)
    mma_gemm<<<dim3(OUTD/BN, RR/BM, 4), 256, SMEM_GEMM>>>(
        pXhi, pXlo, pW1, pP, DIN/4, (size_t)DIN);
    combine1_kernel<<<RR*OUTD/256, 256>>>(b1);

    // GEMM2: H1(1024x1024) * W2^T -> split-K=2 partials (128 CTAs)
    mma_gemm<<<dim3(OUTD/BN, RR/BM, 2), 256, SMEM_GEMM>>>(
        pH1hi, pH1lo, pW2, pP, OUTD/2, (size_t)OUTD);
    combine2_kernel<<<RR*OUTD/256, 256>>>(b2);

    head_kernel<<<RR, 128>>>(pH2, Wcls, bcls, Wreg, breg, proposals, out);
}

// round 13
// speedup vs baseline: 1.4340x; 1.0696x over previous
#include <cuda_runtime.h>
#include <cuda_fp16.h>
#include <cstdint>
#include <math.h>

#define Bb 2
#define Nn 512
#define Cc 256
#define Hh 256
#define Ww 256
#define POOLP 7
#define SRR 2
#define OUTD 1024
#define DIN (Cc*POOLP*POOLP)   // 12544
#define RR (Bb*Nn)             // 1024
#define NCLS 11
#define PI_F 3.14159265358979323846f

// GEMM tiling (mma.sync path, fp16 2-term: Ahi*B + Alo*B)
#define BM 128
#define BN 128
#define BK 32
#define KSP 40                       // padded smem K-stride (halves) -> 80B rows
#define TB (128*KSP*2)               // 10240 bytes per operand tile
#define STAGE (3*TB)                 // Ahi, Alo, B = 30720
#define SMEM_GEMM (2*STAGE)          // 61440 B double buffered -> 2 CTAs/SM

// ------------------------- device scratch (no cudaMalloc) -------------------
__device__ float g_feat_hwc[(size_t)Bb*Hh*Ww*Cc];            // 134 MB NHWC
__device__ __half g_Xhi[(size_t)RR*DIN];
__device__ __half g_Xlo[(size_t)RR*DIN];
__device__ __half g_W1[(size_t)OUTD*DIN];                    // [N,K] K-major fp16
__device__ __half g_W2[(size_t)OUTD*OUTD];
__device__ float g_P[(size_t)4*RR*OUTD];                     // split-K partials
__device__ __half g_H1hi[RR*OUTD];
__device__ __half g_H1lo[RR*OUTD];
__device__ float g_H2[RR*OUTD];

// ------------------------- helpers ------------------------------------------
__device__ __forceinline__ void cp16(uint32_t s, const void* g) {
    asm volatile("cp.async.cg.shared.global [%0], [%1], 16;" :: "r"(s), "l"(g));
}
__device__ __forceinline__ void ldsm4(uint32_t* r, uint32_t addr) {
    asm volatile("ldmatrix.sync.aligned.m8n8.x4.shared.b16 {%0,%1,%2,%3}, [%4];"
                 : "=r"(r[0]), "=r"(r[1]), "=r"(r[2]), "=r"(r[3]) : "r"(addr));
}
#define MMA_F16(D, A, B0, B1)                                                   \
    asm volatile("mma.sync.aligned.m16n8k16.row.col.f32.f16.f16.f32 "           \
                 "{%0,%1,%2,%3}, {%4,%5,%6,%7}, {%8,%9}, {%0,%1,%2,%3};"        \
                 : "+f"((D)[0]), "+f"((D)[1]), "+f"((D)[2]), "+f"((D)[3])       \
                 : "r"((A)[0]), "r"((A)[1]), "r"((A)[2]), "r"((A)[3]),          \
                   "r"(B0), "r"(B1))

// ---------------------------------------------------------------------------
// 1) NCHW -> NHWC transpose
// ---------------------------------------------------------------------------
__global__ void transpose_kernel(const float* __restrict__ in) {
    __shared__ float tile[32][33];
    int b = blockIdx.z;
    const float* A = in + (size_t)b * Cc * Hh * Ww;
    float* O = g_feat_hwc + (size_t)b * Cc * Hh * Ww;
    int p0 = blockIdx.x * 32;
    int c0 = blockIdx.y * 32;
    #pragma unroll
    for (int i = threadIdx.y; i < 32; i += 8)
        tile[i][threadIdx.x] = A[(size_t)(c0 + i) * (Hh * Ww) + p0 + threadIdx.x];
    __syncthreads();
    #pragma unroll
    for (int i = threadIdx.y; i < 32; i += 8)
        O[(size_t)(p0 + i) * Cc + c0 + threadIdx.x] = tile[threadIdx.x][i];
}

// ---------------------------------------------------------------------------
// 1b) Weight transpose + fp16 convert: W[K,N] -> T[N,K]
// ---------------------------------------------------------------------------
__global__ void wconv_kernel(const float* __restrict__ W, __half* __restrict__ T,
                             int K, int N) {
    __shared__ float tile[32][33];
    int k0 = blockIdx.x * 32, n0 = blockIdx.y * 32;
    int tx = threadIdx.x, ty = threadIdx.y;
    #pragma unroll
    for (int i = ty; i < 32; i += 8)
        tile[i][tx] = W[(size_t)(k0 + i) * N + n0 + tx];
    __syncthreads();
    #pragma unroll
    for (int i = ty; i < 32; i += 8)
        T[(size_t)(n0 + i) * K + k0 + tx] = __float2half(tile[tx][i]);
}

// ---------------------------------------------------------------------------
// 2) Rotated ROI align -> X (fp16 hi/lo). No smem output staging: each thread
//    owns one channel (a contiguous 49-elem run of X) and stores directly.
//    smem 31KB -> 6.3KB => ~16 blocks/SM, latency-bound kernel gets 2.5x warps.
// ---------------------------------------------------------------------------
__global__ __launch_bounds__(128) void roi_align_kernel(const float* __restrict__ proposals) {
    __shared__ float4 s_w[POOLP*POOLP*SRR*SRR];
    __shared__ int4   s_o[POOLP*POOLP*SRR*SRR];

    int r = blockIdx.x;
    int chunk = blockIdx.y;
    int b = r / Nn;
    int tid = threadIdx.x;

    const float* pr = proposals + r * 5;
    float cx = pr[0], cy = pr[1], w = pr[2], h = pr[3], th = pr[4];
    float ct = cosf(th), st = sinf(th);

    for (int s = tid; s < POOLP*POOLP*SRR*SRR; s += 128) {
        int bin = s >> 2;
        int by = bin / POOLP, bx = bin % POOLP;
        int sub = s & 3;
        int sy = sub >> 1, sx = sub & 1;
        float yy = -h * 0.5f + (h / (float)POOLP) * ((float)by + ((float)sy + 0.5f) / (float)SRR);
        float xx = -w * 0.5f + (w / (float)POOLP) * ((float)bx + ((float)sx + 0.5f) / (float)SRR);
        float gx = cx + xx * ct - yy * st;
        float gy = cy + xx * st + yy * ct;
        float valid = (gy > -1.f && gy < (float)Hh && gx > -1.f && gx < (float)Ww) ? 1.f : 0.f;
        gy = fminf(fmaxf(gy, 0.f), (float)(Hh - 1));
        gx = fminf(fmaxf(gx, 0.f), (float)(Ww - 1));
        float y0 = floorf(gy), x0 = floorf(gx);
        int y0i = (int)y0, x0i = (int)x0;
        int y1i = min(y0i + 1, Hh - 1), x1i = min(x0i + 1, Ww - 1);
        float ly = gy - y0, lx = gx - x0;
        float hy = 1.f - ly, hx = 1.f - lx;
        float sc = valid * 0.25f;
        s_w[s] = make_float4(hy*hx*sc, hy*lx*sc, ly*hx*sc, ly*lx*sc);
        s_o[s] = make_int4(y0i*Ww + x0i, y0i*Ww + x1i, y1i*Ww + x0i, y1i*Ww + x1i);
    }
    __syncthreads();

    const float* F = g_feat_hwc + (size_t)b * Hh * Ww * Cc;
    int c = chunk * 128 + tid;

    // this thread's contiguous output run: X[r, c*49 .. c*49+48]
    size_t base = (size_t)r * DIN + (size_t)c * 49;
    __half* outHi = g_Xhi + base;
    __half* outLo = g_Xlo + base;

    for (int bin = 0; bin < POOLP*POOLP; bin++) {
        float a0 = 0.f, a1 = 0.f, a2 = 0.f, a3 = 0.f;
        #pragma unroll
        for (int s = 0; s < 4; s++) {
            int si = bin * 4 + s;
            float4 wv = s_w[si];
            int4   ov = s_o[si];
            a0 = fmaf(wv.x, F[(size_t)ov.x * Cc + c], a0);
            a1 = fmaf(wv.y, F[(size_t)ov.y * Cc + c], a1);
            a2 = fmaf(wv.z, F[(size_t)ov.z * Cc + c], a2);
            a3 = fmaf(wv.w, F[(size_t)ov.w * Cc + c], a3);
        }
        float v = (a0 + a1) + (a2 + a3);
        __half hv = __float2half(v);
        outHi[bin] = hv;
        outLo[bin] = __float2half(v - __half2float(hv));
    }
}

// ---------------------------------------------------------------------------
// 3) mma.sync fp16 2-term GEMM. 8 warps (64x32 warp tiles), 2-stage pipeline.
//    P[z] = (Ahi + Alo) * B^T, K-major operands.
// ---------------------------------------------------------------------------
__global__ void __launch_bounds__(256, 2)
mma_gemm(const __half* __restrict__ Ahi, const __half* __restrict__ Alo,
         const __half* __restrict__ Bw, float* __restrict__ Pout,
         int Ksplit, size_t ldk) {
    extern __shared__ char smem[];
    uint32_t sb = (uint32_t)__cvta_generic_to_shared(smem);
    int tid = threadIdx.x;
    int lane = tid & 31, wid = tid >> 5;
    int wm = wid & 1, wn = wid >> 1;              // warps: 2 along M, 4 along N
    int n0 = blockIdx.x * BN, m0 = blockIdx.y * BM, z = blockIdx.z;
    int kbase = z * Ksplit;
    int S = Ksplit / BK;

    auto stage_load = [&](int s) {
        uint32_t buf = sb + (s & 1) * STAGE;
        int kc = kbase + s * BK;
        #pragma unroll
        for (int i = 0; i < 2; i++) {
            int idx = tid + i * 256;
            int row = idx >> 2, kq = idx & 3;
            uint32_t so = (uint32_t)(row * (KSP * 2) + kq * 16);
            size_t ga = (size_t)(m0 + row) * ldk + kc + kq * 8;
            size_t gb = (size_t)(n0 + row) * ldk + kc + kq * 8;
            cp16(buf + 0 * TB + so, Ahi + ga);
            cp16(buf + 1 * TB + so, Alo + ga);
            cp16(buf + 2 * TB + so, Bw + gb);
        }
        asm volatile("cp.async.commit_group;");
    };

    float acc[4][4][4] = {};

    int aRow = lane & 15;
    int aK   = (lane >> 4) * 8;
    int bRow = (lane & 7) + ((lane >> 4) << 3);
    int bK   = ((lane >> 3) & 1) * 8;

    stage_load(0);
    for (int s = 0; s < S; s++) {
        if (s + 1 < S) {
            stage_load(s + 1);
            asm volatile("cp.async.wait_group 1;");
        } else {
            asm volatile("cp.async.wait_group 0;");
        }
        __syncthreads();

        uint32_t buf = sb + (s & 1) * STAGE;
        #pragma unroll
        for (int kk = 0; kk < 2; kk++) {
            int kb = kk * 16;
            uint32_t ah[4][4], al[4][4], bw[8];
            #pragma unroll
            for (int mt = 0; mt < 4; mt++) {
                uint32_t ro = (uint32_t)((wm * 64 + mt * 16 + aRow) * (KSP * 2) + (kb + aK) * 2);
                ldsm4(ah[mt], buf + 0 * TB + ro);
                ldsm4(al[mt], buf + 1 * TB + ro);
            }
            #pragma unroll
            for (int nh = 0; nh < 2; nh++) {
                uint32_t ro = (uint32_t)((wn * 32 + nh * 16 + bRow) * (KSP * 2) + (kb + bK) * 2);
                ldsm4(&bw[nh * 4], buf + 2 * TB + ro);
            }
            #pragma unroll
            for (int mt = 0; mt < 4; mt++)
                #pragma unroll
                for (int nt = 0; nt < 4; nt++) {
                    MMA_F16(acc[mt][nt], ah[mt], bw[nt * 2], bw[nt * 2 + 1]);
                    MMA_F16(acc[mt][nt], al[mt], bw[nt * 2], bw[nt * 2 + 1]);
                }
        }
        __syncthreads();
    }

    // epilogue: raw partials (bias applied in combine)
    int drow = lane >> 2, dcol = (lane & 3) * 2;
    float* Cz = Pout + (size_t)z * RR * OUTD;
    #pragma unroll
    for (int mt = 0; mt < 4; mt++) {
        int m = m0 + wm * 64 + mt * 16 + drow;
        #pragma unroll
        for (int nt = 0; nt < 4; nt++) {
            int n = n0 + wn * 32 + nt * 8 + dcol;
            *reinterpret_cast<float2*>(Cz + (size_t)m * OUTD + n) =
                make_float2(acc[mt][nt][0], acc[mt][nt][1]);
            *reinterpret_cast<float2*>(Cz + (size_t)(m + 8) * OUTD + n) =
                make_float2(acc[mt][nt][2], acc[mt][nt][3]);
        }
    }
}

// ---------------------------------------------------------------------------
// 3b) combine1: sum 4 split-K partials + bias + relu -> H1 fp16 hi/lo
// ---------------------------------------------------------------------------
__global__ void combine1_kernel(const float* __restrict__ b1) {
    int i = blockIdx.x * 256 + threadIdx.x;
    const size_t st = (size_t)RR * OUTD;
    float v = g_P[i] + g_P[st + i] + g_P[2*st + i] + g_P[3*st + i] + b1[i & (OUTD - 1)];
    v = fmaxf(v, 0.f);
    __half h = __float2half(v);
    g_H1hi[i] = h;
    g_H1lo[i] = __float2half(v - __half2float(h));
}

// 3c) combine2: sum 2 split-K partials + bias + relu -> H2 fp32
__global__ void combine2_kernel(const float* __restrict__ b2) {
    int i = blockIdx.x * 256 + threadIdx.x;
    const size_t st = (size_t)RR * OUTD;
    float v = g_P[i] + g_P[st + i] + b2[i & (OUTD - 1)];
    g_H2[i] = fmaxf(v, 0.f);
}

// ---------------------------------------------------------------------------
// 4) Head: cls/reg dots + box decode
// ---------------------------------------------------------------------------
__global__ void head_kernel(const float* __restrict__ X,
                            const float* __restrict__ Wcls, const float* __restrict__ bcls,
                            const float* __restrict__ Wreg, const float* __restrict__ breg,
                            const float* __restrict__ proposals, float* __restrict__ out) {
    __shared__ float xs[OUTD];
    __shared__ float red[16][8];
    __shared__ float regv[5];
    int r = blockIdx.x, t = threadIdx.x;
    const float* xr = X + (size_t)r * OUTD;
    for (int i = t; i < OUTD / 4; i += 128)
        ((float4*)xs)[i] = ((const float4*)xr)[i];
    __syncthreads();

    int j = t & 15, part = t >> 4;
    float acc = 0.f;
    if (j < NCLS) {
        for (int k = part * 128; k < part * 128 + 128; k++)
            acc += xs[k] * Wcls[k * NCLS + j];
    } else {
        int jr = j - NCLS;
        for (int k = part * 128; k < part * 128 + 128; k++)
            acc += xs[k] * Wreg[k * 5 + jr];
    }
    red[j][part] = acc;
    __syncthreads();

    if (t < 16) {
        float s = 0.f;
        #pragma unroll
        for (int p = 0; p < 8; p++) s += red[t][p];
        if (t < NCLS) {
            out[RR * 5 + r * NCLS + t] = s + bcls[t];
        } else {
            regv[t - NCLS] = s + breg[t - NCLS];
        }
    }
    __syncthreads();

    if (t == 0) {
        const float* pr = proposals + r * 5;
        float px = pr[0] * 4.f, py = pr[1] * 4.f;
        float pw = pr[2] * 4.f, ph = pr[3] * 4.f, pa = pr[4];
        const float clampv = 4.135166556742356f;
        float bx = pw * regv[0] + px;
        float by = ph * regv[1] + py;
        float bw = pw * expf(fminf(fmaxf(regv[2], -clampv), clampv));
        float bh = ph * expf(fminf(fmaxf(regv[3], -clampv), clampv));
        float a = pa + regv[4] + PI_F * 0.5f;
        float m = fmodf(a, PI_F);
        if (m < 0.f) m += PI_F;
        out[r * 5 + 0] = bx;
        out[r * 5 + 1] = by;
        out[r * 5 + 2] = bw;
        out[r * 5 + 3] = bh;
        out[r * 5 + 4] = m - PI_F * 0.5f;
    }
}

// ---------------------------------------------------------------------------
extern "C" void kernel_launch(void* const* d_in, const int* in_sizes, int n_in,
                              void* d_out, int out_size) {
    const float* feat      = (const float*)d_in[0];
    const float* proposals = (const float*)d_in[1];
    const float* W1   = (const float*)d_in[2];
    const float* b1   = (const float*)d_in[3];
    const float* W2   = (const float*)d_in[4];
    const float* b2   = (const float*)d_in[5];
    const float* Wcls = (const float*)d_in[6];
    const float* bcls = (const float*)d_in[7];
    const float* Wreg = (const float*)d_in[8];
    const float* breg = (const float*)d_in[9];
    float* out = (float*)d_out;

    __half *pXhi, *pXlo, *pW1, *pW2, *pH1hi, *pH1lo;
    float *pP, *pH2;
    cudaGetSymbolAddress((void**)&pXhi,  g_Xhi);
    cudaGetSymbolAddress((void**)&pXlo,  g_Xlo);
    cudaGetSymbolAddress((void**)&pW1,   g_W1);
    cudaGetSymbolAddress((void**)&pW2,   g_W2);
    cudaGetSymbolAddress((void**)&pH1hi, g_H1hi);
    cudaGetSymbolAddress((void**)&pH1lo, g_H1lo);
    cudaGetSymbolAddress((void**)&pP,    g_P);
    cudaGetSymbolAddress((void**)&pH2,   g_H2);

    cudaFuncSetAttribute(mma_gemm, cudaFuncAttributeMaxDynamicSharedMemorySize, SMEM_GEMM);

    // weight transpose + fp16 convert (independent of feat path)
    wconv_kernel<<<dim3(DIN/32, OUTD/32), dim3(32, 8)>>>(W1, pW1, DIN, OUTD);
    wconv_kernel<<<dim3(OUTD/32, OUTD/32), dim3(32, 8)>>>(W2, pW2, OUTD, OUTD);

    transpose_kernel<<<dim3(Hh*Ww/32, Cc/32, Bb), dim3(32, 8)>>>(feat);
    roi_align_kernel<<<dim3(RR, 2), 128>>>(proposals);

    // GEMM1: X(1024x12544) * W1^T -> split-K=4 partials (256 CTAs, occ 2)
    mma_gemm<<<dim3(OUTD/BN, RR/BM, 4), 256, SMEM_GEMM>>>(
        pXhi, pXlo, pW1, pP, DIN/4, (size_t)DIN);
    combine1_kernel<<<RR*OUTD/256, 256>>>(b1);

    // GEMM2: H1(1024x1024) * W2^T -> split-K=2 partials (128 CTAs)
    mma_gemm<<<dim3(OUTD/BN, RR/BM, 2), 256, SMEM_GEMM>>>(
        pH1hi, pH1lo, pW2, pP, OUTD/2, (size_t)OUTD);
    combine2_kernel<<<RR*OUTD/256, 256>>>(b2);

    head_kernel<<<RR, 128>>>(pH2, Wcls, bcls, Wreg, breg, proposals, out);
}

// round 17
// speedup vs baseline: 1.6709x; 1.1652x over previous
#include <cuda_runtime.h>
#include <cuda_fp16.h>
#include <cstdint>
#include <math.h>

#define Bb 2
#define Nn 512
#define Cc 256
#define Hh 256
#define Ww 256
#define POOLP 7
#define SRR 2
#define OUTD 1024
#define RR (Bb*Nn)             // 1024
#define NCLS 11
#define PI_F 3.14159265358979323846f

#define PB 52                        // padded bins per channel (49 real + 3 zero)
#define KC1 (Cc*PB*2)                // 26624 halves per X row (hi/lo interleaved)
#define KC2 (OUTD*2)                 // 2048 halves per H1 row

// GEMM tiling (single-operand fp16, K' = interleaved hi/lo dim)
#define BM 128
#define BN 128
#define BK 32                        // k' halves per stage
#define KSP 40                       // padded smem K-stride (halves) -> 80B rows
#define TB (128*KSP*2)               // 10240 bytes per operand tile
#define STAGE (2*TB)                 // A, B = 20480
#define SMEM_GEMM (2*STAGE)          // 40960 B double buffered

// ------------------------- device scratch (no cudaMalloc) -------------------
__device__ float g_feat_hwc[(size_t)Bb*Hh*Ww*Cc];            // 134 MB NHWC
__device__ __half g_Xp[(size_t)RR*KC1];                      // 54.5 MB interleaved
__device__ __half g_W1d[(size_t)OUTD*KC1];                   // dup+padded W1
__device__ __half g_W2d[(size_t)OUTD*KC2];                   // dup W2
__device__ float g_P[(size_t)4*RR*OUTD];                     // split-K partials
__device__ __half g_H1p[(size_t)RR*KC2];                     // interleaved H1
__device__ float g_H2[RR*OUTD];

// ------------------------- helpers ------------------------------------------
__device__ __forceinline__ void cp16(uint32_t s, const void* g) {
    asm volatile("cp.async.cg.shared.global [%0], [%1], 16;" :: "r"(s), "l"(g));
}
__device__ __forceinline__ void ldsm4(uint32_t* r, uint32_t addr) {
    asm volatile("ldmatrix.sync.aligned.m8n8.x4.shared.b16 {%0,%1,%2,%3}, [%4];"
                 : "=r"(r[0]), "=r"(r[1]), "=r"(r[2]), "=r"(r[3]) : "r"(addr));
}
#define MMA_F16(D, A, B0, B1)                                                   \
    asm volatile("mma.sync.aligned.m16n8k16.row.col.f32.f16.f16.f32 "           \
                 "{%0,%1,%2,%3}, {%4,%5,%6,%7}, {%8,%9}, {%0,%1,%2,%3};"        \
                 : "+f"((D)[0]), "+f"((D)[1]), "+f"((D)[2]), "+f"((D)[3])       \
                 : "r"((A)[0]), "r"((A)[1]), "r"((A)[2]), "r"((A)[3]),          \
                   "r"(B0), "r"(B1))

__device__ __forceinline__ uint32_t pack_hl(float v) {
    __half hv = __float2half(v);
    __half lv = __float2half(v - __half2float(hv));
    return (uint32_t)__half_as_ushort(hv) | ((uint32_t)__half_as_ushort(lv) << 16);
}

// ---------------------------------------------------------------------------
// 1) NCHW -> NHWC transpose
// ---------------------------------------------------------------------------
__global__ void transpose_kernel(const float* __restrict__ in) {
    __shared__ float tile[32][33];
    int b = blockIdx.z;
    const float* A = in + (size_t)b * Cc * Hh * Ww;
    float* O = g_feat_hwc + (size_t)b * Cc * Hh * Ww;
    int p0 = blockIdx.x * 32;
    int c0 = blockIdx.y * 32;
    #pragma unroll
    for (int i = threadIdx.y; i < 32; i += 8)
        tile[i][threadIdx.x] = A[(size_t)(c0 + i) * (Hh * Ww) + p0 + threadIdx.x];
    __syncthreads();
    #pragma unroll
    for (int i = threadIdx.y; i < 32; i += 8)
        O[(size_t)(p0 + i) * Cc + c0 + threadIdx.x] = tile[threadIdx.x][i];
}

// ---------------------------------------------------------------------------
// 1b) W1 transpose + fp16 dup into padded-K' layout:
//     W1d[n, 2*(c*52+bin)+{0,1}] = fp16(W1[c*49+bin, n])
// ---------------------------------------------------------------------------
__global__ void wconv1_kernel(const float* __restrict__ W) {
    __shared__ float tile[32][33];
    int k0 = blockIdx.x * 32, n0 = blockIdx.y * 32;
    int tx = threadIdx.x, ty = threadIdx.y;
    #pragma unroll
    for (int i = ty; i < 32; i += 8)
        tile[i][tx] = W[(size_t)(k0 + i) * OUTD + n0 + tx];
    __syncthreads();
    int k = k0 + tx;
    int c = k / 49, bin = k - c * 49;
    size_t koff = 2 * (size_t)(c * PB + bin);
    #pragma unroll
    for (int i = ty; i < 32; i += 8) {
        unsigned short hw = __half_as_ushort(__float2half(tile[tx][i]));
        uint32_t dup = (uint32_t)hw | ((uint32_t)hw << 16);
        *reinterpret_cast<uint32_t*>(g_W1d + (size_t)(n0 + i) * KC1 + koff) = dup;
    }
}

// zero the 3 padded bins per channel of W1d
__global__ void wpad1_kernel() {
    int idx = blockIdx.x * 256 + threadIdx.x;          // OUTD*Cc*3
    int n = idx / (Cc * 3);
    int rem = idx - n * (Cc * 3);
    int c = rem / 3, bin = 49 + (rem - c * 3);
    *reinterpret_cast<uint32_t*>(g_W1d + (size_t)n * KC1 + 2 * (size_t)(c * PB + bin)) = 0u;
}

// 1c) W2 transpose + fp16 dup: W2d[n, 2k+{0,1}] = fp16(W2[k, n])
__global__ void wconv2_kernel(const float* __restrict__ W) {
    __shared__ float tile[32][33];
    int k0 = blockIdx.x * 32, n0 = blockIdx.y * 32;
    int tx = threadIdx.x, ty = threadIdx.y;
    #pragma unroll
    for (int i = ty; i < 32; i += 8)
        tile[i][tx] = W[(size_t)(k0 + i) * OUTD + n0 + tx];
    __syncthreads();
    #pragma unroll
    for (int i = ty; i < 32; i += 8) {
        unsigned short hw = __half_as_ushort(__float2half(tile[tx][i]));
        uint32_t dup = (uint32_t)hw | ((uint32_t)hw << 16);
        *reinterpret_cast<uint32_t*>(g_W2d + (size_t)(n0 + i) * KC2 + 2 * (size_t)(k0 + tx)) = dup;
    }
}

// ---------------------------------------------------------------------------
// 2) Rotated ROI align -> Xp (interleaved hi/lo, 52-bin padded runs).
//    Each thread owns one channel; 13 x 16B aligned uint4 stores per thread.
// ---------------------------------------------------------------------------
__global__ __launch_bounds__(128) void roi_align_kernel(const float* __restrict__ proposals) {
    __shared__ float4 s_w[POOLP*POOLP*SRR*SRR];
    __shared__ int4   s_o[POOLP*POOLP*SRR*SRR];

    int r = blockIdx.x;
    int chunk = blockIdx.y;
    int b = r / Nn;
    int tid = threadIdx.x;

    const float* pr = proposals + r * 5;
    float cx = pr[0], cy = pr[1], w = pr[2], h = pr[3], th = pr[4];
    float ct = cosf(th), st = sinf(th);

    for (int s = tid; s < POOLP*POOLP*SRR*SRR; s += 128) {
        int bin = s >> 2;
        int by = bin / POOLP, bx = bin % POOLP;
        int sub = s & 3;
        int sy = sub >> 1, sx = sub & 1;
        float yy = -h * 0.5f + (h / (float)POOLP) * ((float)by + ((float)sy + 0.5f) / (float)SRR);
        float xx = -w * 0.5f + (w / (float)POOLP) * ((float)bx + ((float)sx + 0.5f) / (float)SRR);
        float gx = cx + xx * ct - yy * st;
        float gy = cy + xx * st + yy * ct;
        float valid = (gy > -1.f && gy < (float)Hh && gx > -1.f && gx < (float)Ww) ? 1.f : 0.f;
        gy = fminf(fmaxf(gy, 0.f), (float)(Hh - 1));
        gx = fminf(fmaxf(gx, 0.f), (float)(Ww - 1));
        float y0 = floorf(gy), x0 = floorf(gx);
        int y0i = (int)y0, x0i = (int)x0;
        int y1i = min(y0i + 1, Hh - 1), x1i = min(x0i + 1, Ww - 1);
        float ly = gy - y0, lx = gx - x0;
        float hy = 1.f - ly, hx = 1.f - lx;
        float sc = valid * 0.25f;
        s_w[s] = make_float4(hy*hx*sc, hy*lx*sc, ly*hx*sc, ly*lx*sc);
        s_o[s] = make_int4(y0i*Ww + x0i, y0i*Ww + x1i, y1i*Ww + x0i, y1i*Ww + x1i);
    }
    __syncthreads();

    const float* F = g_feat_hwc + (size_t)b * Hh * Ww * Cc;
    int c = chunk * 128 + tid;

    // this thread's 16B-aligned run: Xp[r, c*52*2 .. ], 52 (hi,lo) pairs
    uint4* outP = reinterpret_cast<uint4*>(g_Xp + (size_t)r * KC1 + (size_t)c * (PB * 2));

    for (int g = 0; g < 13; g++) {
        uint32_t pu[4];
        #pragma unroll
        for (int j = 0; j < 4; j++) {
            int bin = g * 4 + j;
            float v = 0.f;
            if (bin < 49) {
                float a0 = 0.f, a1 = 0.f, a2 = 0.f, a3 = 0.f;
                #pragma unroll
                for (int s = 0; s < 4; s++) {
                    int si = bin * 4 + s;
                    float4 wv = s_w[si];
                    int4   ov = s_o[si];
                    a0 = fmaf(wv.x, F[(size_t)ov.x * Cc + c], a0);
                    a1 = fmaf(wv.y, F[(size_t)ov.y * Cc + c], a1);
                    a2 = fmaf(wv.z, F[(size_t)ov.z * Cc + c], a2);
                    a3 = fmaf(wv.w, F[(size_t)ov.w * Cc + c], a3);
                }
                v = (a0 + a1) + (a2 + a3);
            }
            pu[j] = pack_hl(v);
        }
        outP[g] = make_uint4(pu[0], pu[1], pu[2], pu[3]);
    }
}

// ---------------------------------------------------------------------------
// 3) mma.sync fp16 GEMM over interleaved K'. 8 warps (64x32 warp tiles),
//    2-stage cp.async pipeline. P[z] = A * B^T.
// ---------------------------------------------------------------------------
__global__ void __launch_bounds__(256, 2)
mma_gemm(const __half* __restrict__ Aop, const __half* __restrict__ Bop,
         float* __restrict__ Pout, int Ksplit, size_t ldk) {
    extern __shared__ char smem[];
    uint32_t sb = (uint32_t)__cvta_generic_to_shared(smem);
    int tid = threadIdx.x;
    int lane = tid & 31, wid = tid >> 5;
    int wm = wid & 1, wn = wid >> 1;              // warps: 2 along M, 4 along N
    int n0 = blockIdx.x * BN, m0 = blockIdx.y * BM, z = blockIdx.z;
    int kbase = z * Ksplit;
    int S = Ksplit / BK;

    auto stage_load = [&](int s) {
        uint32_t buf = sb + (s & 1) * STAGE;
        int kc = kbase + s * BK;
        #pragma unroll
        for (int i = 0; i < 2; i++) {
            int idx = tid + i * 256;
            int row = idx >> 2, kq = idx & 3;
            uint32_t so = (uint32_t)(row * (KSP * 2) + kq * 16);
            cp16(buf + 0 * TB + so, Aop + (size_t)(m0 + row) * ldk + kc + kq * 8);
            cp16(buf + 1 * TB + so, Bop + (size_t)(n0 + row) * ldk + kc + kq * 8);
        }
        asm volatile("cp.async.commit_group;");
    };

    float acc[4][4][4] = {};

    int aRow = lane & 15;
    int aK   = (lane >> 4) * 8;
    int bRow = (lane & 7) + ((lane >> 4) << 3);
    int bK   = ((lane >> 3) & 1) * 8;

    stage_load(0);
    for (int s = 0; s < S; s++) {
        if (s + 1 < S) {
            stage_load(s + 1);
            asm volatile("cp.async.wait_group 1;");
        } else {
            asm volatile("cp.async.wait_group 0;");
        }
        __syncthreads();

        uint32_t buf = sb + (s & 1) * STAGE;
        #pragma unroll
        for (int kk = 0; kk < 2; kk++) {
            int kb = kk * 16;
            uint32_t ah[4][4], bw[8];
            #pragma unroll
            for (int mt = 0; mt < 4; mt++) {
                uint32_t ro = (uint32_t)((wm * 64 + mt * 16 + aRow) * (KSP * 2) + (kb + aK) * 2);
                ldsm4(ah[mt], buf + 0 * TB + ro);
            }
            #pragma unroll
            for (int nh = 0; nh < 2; nh++) {
                uint32_t ro = (uint32_t)((wn * 32 + nh * 16 + bRow) * (KSP * 2) + (kb + bK) * 2);
                ldsm4(&bw[nh * 4], buf + 1 * TB + ro);
            }
            #pragma unroll
            for (int mt = 0; mt < 4; mt++)
                #pragma unroll
                for (int nt = 0; nt < 4; nt++)
                    MMA_F16(acc[mt][nt], ah[mt], bw[nt * 2], bw[nt * 2 + 1]);
        }
        __syncthreads();
    }

    int drow = lane >> 2, dcol = (lane & 3) * 2;
    float* Cz = Pout + (size_t)z * RR * OUTD;
    #pragma unroll
    for (int mt = 0; mt < 4; mt++) {
        int m = m0 + wm * 64 + mt * 16 + drow;
        #pragma unroll
        for (int nt = 0; nt < 4; nt++) {
            int n = n0 + wn * 32 + nt * 8 + dcol;
            *reinterpret_cast<float2*>(Cz + (size_t)m * OUTD + n) =
                make_float2(acc[mt][nt][0], acc[mt][nt][1]);
            *reinterpret_cast<float2*>(Cz + (size_t)(m + 8) * OUTD + n) =
                make_float2(acc[mt][nt][2], acc[mt][nt][3]);
        }
    }
}

// ---------------------------------------------------------------------------
// 3b) combine1: sum 4 split-K partials + bias + relu -> H1 interleaved hi/lo
// ---------------------------------------------------------------------------
__global__ void combine1_kernel(const float* __restrict__ b1) {
    int i = blockIdx.x * 256 + threadIdx.x;
    const size_t st = (size_t)RR * OUTD;
    float v = g_P[i] + g_P[st + i] + g_P[2*st + i] + g_P[3*st + i] + b1[i & (OUTD - 1)];
    v = fmaxf(v, 0.f);
    *reinterpret_cast<uint32_t*>(g_H1p + 2 * (size_t)i) = pack_hl(v);
}

// 3c) combine2: sum 2 split-K partials + bias + relu -> H2 fp32
__global__ void combine2_kernel(const float* __restrict__ b2) {
    int i = blockIdx.x * 256 + threadIdx.x;
    const size_t st = (size_t)RR * OUTD;
    float v = g_P[i] + g_P[st + i] + b2[i & (OUTD - 1)];
    g_H2[i] = fmaxf(v, 0.f);
}

// ---------------------------------------------------------------------------
// 4) Head: cls/reg dots + box decode
// ---------------------------------------------------------------------------
__global__ void head_kernel(const float* __restrict__ X,
                            const float* __restrict__ Wcls, const float* __restrict__ bcls,
                            const float* __restrict__ Wreg, const float* __restrict__ breg,
                            const float* __restrict__ proposals, float* __restrict__ out) {
    __shared__ float xs[OUTD];
    __shared__ float red[16][8];
    __shared__ float regv[5];
    int r = blockIdx.x, t = threadIdx.x;
    const float* xr = X + (size_t)r * OUTD;
    for (int i = t; i < OUTD / 4; i += 128)
        ((float4*)xs)[i] = ((const float4*)xr)[i];
    __syncthreads();

    int j = t & 15, part = t >> 4;
    float acc = 0.f;
    if (j < NCLS) {
        for (int k = part * 128; k < part * 128 + 128; k++)
            acc += xs[k] * Wcls[k * NCLS + j];
    } else {
        int jr = j - NCLS;
        for (int k = part * 128; k < part * 128 + 128; k++)
            acc += xs[k] * Wreg[k * 5 + jr];
    }
    red[j][part] = acc;
    __syncthreads();

    if (t < 16) {
        float s = 0.f;
        #pragma unroll
        for (int p = 0; p < 8; p++) s += red[t][p];
        if (t < NCLS) {
            out[RR * 5 + r * NCLS + t] = s + bcls[t];
        } else {
            regv[t - NCLS] = s + breg[t - NCLS];
        }
    }
    __syncthreads();

    if (t == 0) {
        const float* pr = proposals + r * 5;
        float px = pr[0] * 4.f, py = pr[1] * 4.f;
        float pw = pr[2] * 4.f, ph = pr[3] * 4.f, pa = pr[4];
        const float clampv = 4.135166556742356f;
        float bx = pw * regv[0] + px;
        float by = ph * regv[1] + py;
        float bw = pw * expf(fminf(fmaxf(regv[2], -clampv), clampv));
        float bh = ph * expf(fminf(fmaxf(regv[3], -clampv), clampv));
        float a = pa + regv[4] + PI_F * 0.5f;
        float m = fmodf(a, PI_F);
        if (m < 0.f) m += PI_F;
        out[r * 5 + 0] = bx;
        out[r * 5 + 1] = by;
        out[r * 5 + 2] = bw;
        out[r * 5 + 3] = bh;
        out[r * 5 + 4] = m - PI_F * 0.5f;
    }
}

// ---------------------------------------------------------------------------
extern "C" void kernel_launch(void* const* d_in, const int* in_sizes, int n_in,
                              void* d_out, int out_size) {
    const float* feat      = (const float*)d_in[0];
    const float* proposals = (const float*)d_in[1];
    const float* W1   = (const float*)d_in[2];
    const float* b1   = (const float*)d_in[3];
    const float* W2   = (const float*)d_in[4];
    const float* b2   = (const float*)d_in[5];
    const float* Wcls = (const float*)d_in[6];
    const float* bcls = (const float*)d_in[7];
    const float* Wreg = (const float*)d_in[8];
    const float* breg = (const float*)d_in[9];
    float* out = (float*)d_out;

    __half *pXp, *pW1d, *pW2d, *pH1p;
    float *pP, *pH2;
    cudaGetSymbolAddress((void**)&pXp,  g_Xp);
    cudaGetSymbolAddress((void**)&pW1d, g_W1d);
    cudaGetSymbolAddress((void**)&pW2d, g_W2d);
    cudaGetSymbolAddress((void**)&pH1p, g_H1p);
    cudaGetSymbolAddress((void**)&pP,   g_P);
    cudaGetSymbolAddress((void**)&pH2,  g_H2);

    cudaFuncSetAttribute(mma_gemm, cudaFuncAttributeMaxDynamicSharedMemorySize, SMEM_GEMM);

    // weight prep (independent of feat path)
    wconv1_kernel<<<dim3(Cc*POOLP*POOLP/32, OUTD/32), dim3(32, 8)>>>(W1);
    wpad1_kernel<<<OUTD*Cc*3/256, 256>>>();
    wconv2_kernel<<<dim3(OUTD/32, OUTD/32), dim3(32, 8)>>>(W2);

    transpose_kernel<<<dim3(Hh*Ww/32, Cc/32, Bb), dim3(32, 8)>>>(feat);
    roi_align_kernel<<<dim3(RR, 2), 128>>>(proposals);

    // GEMM1: Xp(1024 x 26624) * W1d^T -> split-K=4 partials
    mma_gemm<<<dim3(OUTD/BN, RR/BM, 4), 256, SMEM_GEMM>>>(
        pXp, pW1d, pP, KC1/4, (size_t)KC1);
    combine1_kernel<<<RR*OUTD/256, 256>>>(b1);

    // GEMM2: H1p(1024 x 2048) * W2d^T -> split-K=2 partials
    mma_gemm<<<dim3(OUTD/BN, RR/BM, 2), 256, SMEM_GEMM>>>(
        pH1p, pW2d, pP, KC2/2, (size_t)KC2);
    combine2_kernel<<<RR*OUTD/256, 256>>>(b2);

    head_kernel<<<RR, 128>>>(pH2, Wcls, bcls, Wreg, breg, proposals, out);
}